// round 10
// baseline (speedup 1.0000x reference)
#include <cuda_runtime.h>
#include <cuda_fp16.h>
#include <cstdint>

#define NB 8
#define SS 2048
#define DD 512
#define MTOT (NB*SS)   // 16384

// GEMM tile: BM=128, BN=256, BK=64 halfs. 8 warps (wm in {0,1}, wn in {0..3}),
// warp tile 64x64 via 4x8 m16n8k16 fp16 fragments (fp32 accum).
// SMEM rows: 32 words + 4 pad = 36 words (144B); ldmatrix conflict-free
// (144 mod 128 = 16 -> 8 row-chunks hit distinct 16B slots).
#define BKH 64
#define PAD 36
#define AW (128*PAD)              // 4608 words
#define BW (256*PAD)              // 9216 words
#define STG_W (AW + BW)           // 13824 words = 55296 B
#define NSTAGE 4
#define SMEM_BYTES (NSTAGE*STG_W*4)   // 221184

// ---- scratch (static; no dynamic allocation) ----
__device__ __align__(128) __half g_qh [(size_t)MTOT*DD];
__device__ __align__(128) __half g_kh [(size_t)MTOT*DD];
__device__ __align__(128) __half g_vh [(size_t)MTOT*DD];
__device__ __align__(128) __half g_wt [(size_t)3*DD*DD];    // [z][n][k]
__device__ __align__(128) __half g_qph[(size_t)MTOT*DD];
__device__ __align__(128) __half g_kph[(size_t)MTOT*DD];
__device__ __align__(128) __half g_vpt[(size_t)MTOT*DD];    // [b][d][s]
__device__ __align__(128) __half g_exph[(size_t)NB*SS*SS];  // 67 MB
__device__ float g_rowsum[MTOT];

// ---- ptx helpers ----
__device__ __forceinline__ unsigned sptr(const void* p){
    return (unsigned)__cvta_generic_to_shared(p);
}
__device__ __forceinline__ void cp16(unsigned s, const void* g){
    asm volatile("cp.async.cg.shared.global [%0], [%1], 16;" :: "r"(s), "l"(g));
}
__device__ __forceinline__ void cp_commit(){ asm volatile("cp.async.commit_group;"); }
__device__ __forceinline__ void cp_wait2(){ asm volatile("cp.async.wait_group 2;"); }
__device__ __forceinline__ void cp_wait1(){ asm volatile("cp.async.wait_group 1;"); }
__device__ __forceinline__ void cp_wait0(){ asm volatile("cp.async.wait_group 0;"); }

__device__ __forceinline__ void mma16(float* d, const unsigned* a, const unsigned* b){
    asm volatile("mma.sync.aligned.m16n8k16.row.col.f32.f16.f16.f32 "
        "{%0,%1,%2,%3}, {%4,%5,%6,%7}, {%8,%9}, {%0,%1,%2,%3};"
        : "+f"(d[0]), "+f"(d[1]), "+f"(d[2]), "+f"(d[3])
        : "r"(a[0]), "r"(a[1]), "r"(a[2]), "r"(a[3]),
          "r"(b[0]), "r"(b[1]));
}
__device__ __forceinline__ void ldsm4(unsigned* r, uint32_t addr){
    asm volatile("ldmatrix.sync.aligned.m8n8.x4.shared.b16 {%0,%1,%2,%3}, [%4];"
        : "=r"(r[0]), "=r"(r[1]), "=r"(r[2]), "=r"(r[3]) : "r"(addr));
}

// ---- async tile loaders (256 threads). lda/ldb in halfs. ----
__device__ __forceinline__ void load_A(unsigned* As, const __half* A, int lda){
    int tid = threadIdx.x;
    #pragma unroll
    for (int i = 0; i < 4; i++){              // 128 rows x 8 chunks(16B)
        int id = tid + i*256;
        int r = id >> 3, ch = id & 7;
        cp16(sptr(As + r*PAD + ch*4), A + (size_t)r*lda + ch*8);
    }
}
__device__ __forceinline__ void load_B(unsigned* Bs, const __half* B, int ldb){
    int tid = threadIdx.x;
    #pragma unroll
    for (int i = 0; i < 8; i++){              // 256 rows x 8 chunks
        int id = tid + i*256;
        int r = id >> 3, ch = id & 7;
        cp16(sptr(Bs + r*PAD + ch*4), B + (size_t)r*ldb + ch*8);
    }
}

// C[128,256] = A[128,K] @ B[256,K]^T; 4-stage cp.async ring, 1 barrier/iter,
// ldmatrix fragment loads.
__device__ __forceinline__ void gemm_main(unsigned* sh,
    const __half* A, int lda, const __half* B, int ldb, int nk, float acc[4][8][4])
{
    #pragma unroll
    for (int p = 0; p < 3; p++){
        load_A(sh + p*STG_W,      A + (size_t)p*BKH, lda);
        load_B(sh + p*STG_W + AW, B + (size_t)p*BKH, ldb);
        cp_commit();
    }

    int lane = threadIdx.x & 31, warp = threadIdx.x >> 5;
    int wm = warp & 1, wn = warp >> 1;
    int laneRow = (lane & 7) + ((lane >> 3) & 1)*8;   // matrix row within 16
    int laneCol = (lane >> 4)*4;                      // 0 or 4 words (k block)
    uint32_t sb = sptr(sh);
    uint32_t aOff = ((wm*64 + laneRow)*PAD + laneCol)*4;
    uint32_t bOff = (AW + (wn*64 + laneRow)*PAD + laneCol)*4;

    int s = 0;
    for (int it = 0; it < nk; it++){
        int rem = nk - it - 1;
        if (rem >= 2) cp_wait2(); else if (rem == 1) cp_wait1(); else cp_wait0();
        __syncthreads();
        if (it + 3 < nk){
            int sn = s + 3; if (sn >= NSTAGE) sn -= NSTAGE;
            load_A(sh + sn*STG_W,      A + (size_t)(it+3)*BKH, lda);
            load_B(sh + sn*STG_W + AW, B + (size_t)(it+3)*BKH, ldb);
            cp_commit();
        }
        uint32_t sA = sb + s*(STG_W*4) + aOff;
        uint32_t sB = sb + s*(STG_W*4) + bOff;
        #pragma unroll
        for (int ks = 0; ks < 4; ks++){                  // 4 k-steps of 16
            unsigned a[4][4], b[4][4];
            #pragma unroll
            for (int mi = 0; mi < 4; mi++) ldsm4(a[mi], sA + mi*(16*PAD*4) + ks*32);
            #pragma unroll
            for (int p = 0; p < 4; p++)    ldsm4(b[p],  sB + p*(16*PAD*4) + ks*32);
            #pragma unroll
            for (int p = 0; p < 4; p++){
                unsigned b0[2] = { b[p][0], b[p][2] };   // ni = 2p
                unsigned b1[2] = { b[p][1], b[p][3] };   // ni = 2p+1
                #pragma unroll
                for (int mi = 0; mi < 4; mi++){
                    mma16(acc[mi][2*p],   a[mi], b0);
                    mma16(acc[mi][2*p+1], a[mi], b1);
                }
            }
        }
        s++; if (s == NSTAGE) s = 0;
    }
}

// ================= prep kernels =================
__global__ void cvt_half(const float4* q, const float4* k, const float4* v){
    const float4* src = (blockIdx.z == 0) ? q : (blockIdx.z == 1) ? k : v;
    __half* dst = (blockIdx.z == 0) ? g_qh : (blockIdx.z == 1) ? g_kh : g_vh;
    size_t i = (size_t)blockIdx.x*blockDim.x + threadIdx.x;
    float4 a = src[2*i], b = src[2*i+1];
    __half2 h[4];
    h[0] = __floats2half2_rn(a.x, a.y);
    h[1] = __floats2half2_rn(a.z, a.w);
    h[2] = __floats2half2_rn(b.x, b.y);
    h[3] = __floats2half2_rn(b.z, b.w);
    *(uint4*)(dst + 8*i) = *(uint4*)h;
}

__global__ void wt_t(const float* Wq, const float* Wk, const float* Wv){
    __shared__ float t[32][33];
    const float* W = (blockIdx.z == 0) ? Wq : (blockIdx.z == 1) ? Wk : Wv;
    int bn = blockIdx.x*32, bk = blockIdx.y*32;
    int tx = threadIdx.x, ty = threadIdx.y;                   // 32 x 8
    #pragma unroll
    for (int j = 0; j < 4; j++)
        t[ty + 8*j][tx] = W[(size_t)(bk + ty + 8*j)*DD + bn + tx];
    __syncthreads();
    __half* O = g_wt + (size_t)blockIdx.z*DD*DD;
    #pragma unroll
    for (int j = 0; j < 4; j++)
        O[(size_t)(bn + ty + 8*j)*DD + bk + tx] = __float2half_rn(t[tx][ty + 8*j]);
}

// ================= GEMM kernels =================
__global__ __launch_bounds__(256, 1) void proj_tc(const float* bq, const float* bk, const float* bv){
    extern __shared__ unsigned sh[];
    int z = blockIdx.z;
    const __half* A = (z == 0) ? g_qh : (z == 1) ? g_kh : g_vh;
    const __half* B = g_wt + (size_t)z*DD*DD;
    const float* bias = (z == 0) ? bq : (z == 1) ? bk : bv;
    int m0 = blockIdx.y*128, n0 = blockIdx.x*256;
    float acc[4][8][4] = {};
    gemm_main(sh, A + (size_t)m0*DD, DD, B + (size_t)n0*DD, DD, DD/BKH, acc);

    int lane = threadIdx.x & 31, warp = threadIdx.x >> 5;
    int wm = warp & 1, wn = warp >> 1;
    int g = lane >> 2, tg = lane & 3;
    if (z < 2){
        __half* C = (z == 0) ? g_qph : g_kph;
        #pragma unroll
        for (int mi = 0; mi < 4; mi++){
            int r = m0 + wm*64 + mi*16 + g;
            #pragma unroll
            for (int ni = 0; ni < 8; ni++){
                int c = n0 + wn*64 + ni*8 + 2*tg;
                float2 bb = *(const float2*)(bias + c);
                *(__half2*)(C + (size_t)r*DD + c) =
                    __floats2half2_rn(acc[mi][ni][0] + bb.x, acc[mi][ni][1] + bb.y);
                *(__half2*)(C + (size_t)(r+8)*DD + c) =
                    __floats2half2_rn(acc[mi][ni][2] + bb.x, acc[mi][ni][3] + bb.y);
            }
        }
    } else {
        int b = m0 >> 11, s0 = m0 & (SS-1);
        #pragma unroll
        for (int mi = 0; mi < 4; mi++){
            int s = s0 + wm*64 + mi*16 + g;
            #pragma unroll
            for (int ni = 0; ni < 8; ni++){
                int c = n0 + wn*64 + ni*8 + 2*tg;
                float2 bb = *(const float2*)(bias + c);
                __half* base0 = g_vpt + (size_t)(b*DD + c)*SS;
                __half* base1 = g_vpt + (size_t)(b*DD + c + 1)*SS;
                base0[s]   = __float2half_rn(acc[mi][ni][0] + bb.x);
                base1[s]   = __float2half_rn(acc[mi][ni][1] + bb.y);
                base0[s+8] = __float2half_rn(acc[mi][ni][2] + bb.x);
                base1[s+8] = __float2half_rn(acc[mi][ni][3] + bb.y);
            }
        }
    }
}

__global__ __launch_bounds__(256, 1) void scores_tc(){
    extern __shared__ unsigned sh[];
    int b = blockIdx.z;
    int m0 = blockIdx.y*128, n0 = blockIdx.x*256;
    float acc[4][8][4] = {};
    gemm_main(sh, g_qph + (size_t)(b*SS + m0)*DD, DD,
                  g_kph + (size_t)(b*SS + n0)*DD, DD, DD/BKH, acc);

    const float scale = 0.04419417382415922f;   // 1/sqrt(512)
    int lane = threadIdx.x & 31, warp = threadIdx.x >> 5;
    int wm = warp & 1, wn = warp >> 1;
    int g = lane >> 2, tg = lane & 3;
    __half* C = g_exph + (size_t)b*SS*SS;
    float rs[4][2] = {};
    #pragma unroll
    for (int mi = 0; mi < 4; mi++){
        int r = m0 + wm*64 + mi*16 + g;
        #pragma unroll
        for (int ni = 0; ni < 8; ni++){
            int c = n0 + wn*64 + ni*8 + 2*tg;
            float e0 = __expf(acc[mi][ni][0]*scale);
            float e1 = __expf(acc[mi][ni][1]*scale);
            float e2 = __expf(acc[mi][ni][2]*scale);
            float e3 = __expf(acc[mi][ni][3]*scale);
            *(__half2*)(C + (size_t)r*SS + c)     = __floats2half2_rn(e0, e1);
            *(__half2*)(C + (size_t)(r+8)*SS + c) = __floats2half2_rn(e2, e3);
            rs[mi][0] += e0 + e1;
            rs[mi][1] += e2 + e3;
        }
    }
    #pragma unroll
    for (int mi = 0; mi < 4; mi++){
        #pragma unroll
        for (int h = 0; h < 2; h++){
            float v = rs[mi][h];
            v += __shfl_xor_sync(0xffffffffu, v, 1);
            v += __shfl_xor_sync(0xffffffffu, v, 2);
            if (tg == 0)
                atomicAdd(&g_rowsum[b*SS + m0 + wm*64 + mi*16 + g + h*8], v);
        }
    }
}

__global__ __launch_bounds__(256, 1) void pv_tc(float* out){
    extern __shared__ unsigned sh[];
    int b = blockIdx.z;
    int m0 = blockIdx.y*128, n0 = blockIdx.x*256;
    float acc[4][8][4] = {};
    gemm_main(sh, g_exph + (size_t)(b*SS + m0)*SS, SS,
                  g_vpt  + (size_t)(b*DD + n0)*SS, SS, SS/BKH, acc);

    int lane = threadIdx.x & 31, warp = threadIdx.x >> 5;
    int wm = warp & 1, wn = warp >> 1;
    int g = lane >> 2, tg = lane & 3;
    #pragma unroll
    for (int mi = 0; mi < 4; mi++){
        int r = m0 + wm*64 + mi*16 + g;
        float inv0 = 1.0f / g_rowsum[b*SS + r];
        float inv1 = 1.0f / g_rowsum[b*SS + r + 8];
        #pragma unroll
        for (int ni = 0; ni < 8; ni++){
            int c = n0 + wn*64 + ni*8 + 2*tg;
            *(float2*)(out + (size_t)(b*SS + r)*DD + c) =
                make_float2(acc[mi][ni][0]*inv0, acc[mi][ni][1]*inv0);
            *(float2*)(out + (size_t)(b*SS + r + 8)*DD + c) =
                make_float2(acc[mi][ni][2]*inv1, acc[mi][ni][3]*inv1);
        }
    }
}

// ================= launch =================
extern "C" void kernel_launch(void* const* d_in, const int* in_sizes, int n_in,
                              void* d_out, int out_size)
{
    const float* q  = (const float*)d_in[0];
    const float* k  = (const float*)d_in[1];
    const float* v  = (const float*)d_in[2];
    const float* Wq = (const float*)d_in[3];
    const float* bq = (const float*)d_in[4];
    const float* Wk = (const float*)d_in[5];
    const float* bk = (const float*)d_in[6];
    const float* Wv = (const float*)d_in[7];
    const float* bv = (const float*)d_in[8];
    float* out = (float*)d_out;

    cudaFuncSetAttribute(proj_tc,   cudaFuncAttributeMaxDynamicSharedMemorySize, SMEM_BYTES);
    cudaFuncSetAttribute(scores_tc, cudaFuncAttributeMaxDynamicSharedMemorySize, SMEM_BYTES);
    cudaFuncSetAttribute(pv_tc,     cudaFuncAttributeMaxDynamicSharedMemorySize, SMEM_BYTES);

    void* p_rowsum;
    cudaGetSymbolAddress(&p_rowsum, g_rowsum);

    cvt_half<<<dim3(4096, 1, 3), 256>>>((const float4*)q, (const float4*)k, (const float4*)v);
    wt_t<<<dim3(16, 16, 3), dim3(32, 8)>>>(Wq, Wk, Wv);
    cudaMemsetAsync(p_rowsum, 0, MTOT*sizeof(float));

    proj_tc  <<<dim3(2, 128, 3), 256, SMEM_BYTES>>>(bq, bk, bv);
    scores_tc<<<dim3(8, 16, 8),  256, SMEM_BYTES>>>();
    pv_tc    <<<dim3(2, 16, 8),  256, SMEM_BYTES>>>(out);
}

// round 11
// speedup vs baseline: 1.1204x; 1.1204x over previous
#include <cuda_runtime.h>
#include <cuda_fp16.h>
#include <cstdint>

#define NB 8
#define SS 2048
#define DD 512
#define MTOT (NB*SS)   // 16384

// GEMM tile: BM=128, BN=128, BK=64 halfs. 8 warps (wm in {0,1}, wn in {0..3}),
// warp tile 64x32 via 4x4 m16n8k16 fp16 fragments (fp32 accum).
// 2 CTAs/SM (regs<=128 via launch_bounds, smem 110592B x2 = 221KB).
// SMEM rows: 32 words + 4 pad = 36; scalar LDS fragment loads, conflict-free.
#define BKH 64
#define PAD 36
#define AW (128*PAD)              // 4608 words
#define BW (128*PAD)              // 4608 words
#define STG_W (AW + BW)           // 9216 words = 36864 B
#define NSTAGE 3
#define SMEM_BYTES (NSTAGE*STG_W*4)   // 110592

// ---- scratch (static; no dynamic allocation) ----
__device__ __align__(128) __half g_qh [(size_t)MTOT*DD];
__device__ __align__(128) __half g_kh [(size_t)MTOT*DD];
__device__ __align__(128) __half g_vh [(size_t)MTOT*DD];
__device__ __align__(128) __half g_wt [(size_t)3*DD*DD];    // [z][n][k]
__device__ __align__(128) __half g_qph[(size_t)MTOT*DD];
__device__ __align__(128) __half g_kph[(size_t)MTOT*DD];
__device__ __align__(128) __half g_vpt[(size_t)MTOT*DD];    // [b][d][s]
__device__ __align__(128) __half g_exph[(size_t)NB*SS*SS];  // 67 MB
__device__ float g_rowsum[MTOT];

// ---- ptx helpers ----
__device__ __forceinline__ unsigned sptr(const void* p){
    return (unsigned)__cvta_generic_to_shared(p);
}
__device__ __forceinline__ void cp16(unsigned s, const void* g){
    asm volatile("cp.async.cg.shared.global [%0], [%1], 16;" :: "r"(s), "l"(g));
}
__device__ __forceinline__ void cp_commit(){ asm volatile("cp.async.commit_group;"); }
__device__ __forceinline__ void cp_wait2(){ asm volatile("cp.async.wait_group 2;"); }
__device__ __forceinline__ void cp_wait1(){ asm volatile("cp.async.wait_group 1;"); }
__device__ __forceinline__ void cp_wait0(){ asm volatile("cp.async.wait_group 0;"); }

__device__ __forceinline__ void mma16(float* d, const unsigned* a, const unsigned* b){
    asm volatile("mma.sync.aligned.m16n8k16.row.col.f32.f16.f16.f32 "
        "{%0,%1,%2,%3}, {%4,%5,%6,%7}, {%8,%9}, {%0,%1,%2,%3};"
        : "+f"(d[0]), "+f"(d[1]), "+f"(d[2]), "+f"(d[3])
        : "r"(a[0]), "r"(a[1]), "r"(a[2]), "r"(a[3]),
          "r"(b[0]), "r"(b[1]));
}

// ---- async tile loaders (256 threads). ld strides in halfs. 128x64 tile ----
__device__ __forceinline__ void load_T(unsigned* Ts, const __half* T, int ld){
    int tid = threadIdx.x;
    #pragma unroll
    for (int i = 0; i < 4; i++){              // 128 rows x 8 chunks(16B)
        int id = tid + i*256;
        int r = id >> 3, ch = id & 7;
        cp16(sptr(Ts + r*PAD + ch*4), T + (size_t)r*ld + ch*8);
    }
}

// one BK=64 tile of MMAs for a 64x32 warp tile
__device__ __forceinline__ void mma_tile(float acc[4][4][4], const unsigned* As, const unsigned* Bs){
    int lane = threadIdx.x & 31, warp = threadIdx.x >> 5;
    int wm = warp & 1, wn = warp >> 1;
    int g = lane >> 2, tg = lane & 3;
    #pragma unroll
    for (int ks = 0; ks < 4; ks++){           // 4 k-steps of 16
        int w0 = ks*8 + tg;
        unsigned a[4][4];
        #pragma unroll
        for (int mi = 0; mi < 4; mi++){
            int r = wm*64 + mi*16 + g;
            a[mi][0] = As[r*PAD + w0];
            a[mi][1] = As[(r+8)*PAD + w0];
            a[mi][2] = As[r*PAD + w0 + 4];
            a[mi][3] = As[(r+8)*PAD + w0 + 4];
        }
        #pragma unroll
        for (int ni = 0; ni < 4; ni++){
            int n = wn*32 + ni*8 + g;
            unsigned b[2];
            b[0] = Bs[n*PAD + w0];
            b[1] = Bs[n*PAD + w0 + 4];
            #pragma unroll
            for (int mi = 0; mi < 4; mi++)
                mma16(acc[mi][ni], a[mi], b);
        }
    }
}

// C[128,128] = A[128,K] @ B[128,K]^T, 3-stage cp.async ring
__device__ __forceinline__ void gemm_main(unsigned* sh,
    const __half* A, int lda, const __half* B, int ldb, int nk, float acc[4][4][4])
{
    load_T(sh, A, lda);
    load_T(sh + AW, B, ldb);
    cp_commit();
    load_T(sh + STG_W, A + BKH, lda);
    load_T(sh + STG_W + AW, B + BKH, ldb);
    cp_commit();

    int s = 0;
    for (int it = 0; it < nk; it++){
        int nx = it + 2;
        if (nx < nk){
            int sn = s + 2; if (sn >= NSTAGE) sn -= NSTAGE;
            load_T(sh + sn*STG_W,      A + (size_t)nx*BKH, lda);
            load_T(sh + sn*STG_W + AW, B + (size_t)nx*BKH, ldb);
            cp_commit();
            cp_wait2();
        } else {
            if (nk - 1 - it == 1) cp_wait1(); else cp_wait0();
        }
        __syncthreads();
        mma_tile(acc, sh + s*STG_W, sh + s*STG_W + AW);
        __syncthreads();
        s++; if (s == NSTAGE) s = 0;
    }
}

// ================= prep kernels =================
__global__ void cvt_half(const float4* q, const float4* k, const float4* v){
    const float4* src = (blockIdx.z == 0) ? q : (blockIdx.z == 1) ? k : v;
    __half* dst = (blockIdx.z == 0) ? g_qh : (blockIdx.z == 1) ? g_kh : g_vh;
    size_t i = (size_t)blockIdx.x*blockDim.x + threadIdx.x;
    float4 a = src[2*i], b = src[2*i+1];
    __half2 h[4];
    h[0] = __floats2half2_rn(a.x, a.y);
    h[1] = __floats2half2_rn(a.z, a.w);
    h[2] = __floats2half2_rn(b.x, b.y);
    h[3] = __floats2half2_rn(b.z, b.w);
    *(uint4*)(dst + 8*i) = *(uint4*)h;
}

__global__ void wt_t(const float* Wq, const float* Wk, const float* Wv){
    __shared__ float t[32][33];
    const float* W = (blockIdx.z == 0) ? Wq : (blockIdx.z == 1) ? Wk : Wv;
    int bn = blockIdx.x*32, bk = blockIdx.y*32;
    int tx = threadIdx.x, ty = threadIdx.y;                   // 32 x 8
    #pragma unroll
    for (int j = 0; j < 4; j++)
        t[ty + 8*j][tx] = W[(size_t)(bk + ty + 8*j)*DD + bn + tx];
    __syncthreads();
    __half* O = g_wt + (size_t)blockIdx.z*DD*DD;
    #pragma unroll
    for (int j = 0; j < 4; j++)
        O[(size_t)(bn + ty + 8*j)*DD + bk + tx] = __float2half_rn(t[tx][ty + 8*j]);
}

// ================= GEMM kernels =================
__global__ __launch_bounds__(256, 2) void proj_tc(const float* bq, const float* bk, const float* bv){
    extern __shared__ unsigned sh[];
    int z = blockIdx.z;
    const __half* A = (z == 0) ? g_qh : (z == 1) ? g_kh : g_vh;
    const __half* B = g_wt + (size_t)z*DD*DD;
    const float* bias = (z == 0) ? bq : (z == 1) ? bk : bv;
    int m0 = blockIdx.y*128, n0 = blockIdx.x*128;
    float acc[4][4][4] = {};
    gemm_main(sh, A + (size_t)m0*DD, DD, B + (size_t)n0*DD, DD, DD/BKH, acc);

    int lane = threadIdx.x & 31, warp = threadIdx.x >> 5;
    int wm = warp & 1, wn = warp >> 1;
    int g = lane >> 2, tg = lane & 3;
    if (z < 2){
        __half* C = (z == 0) ? g_qph : g_kph;
        #pragma unroll
        for (int mi = 0; mi < 4; mi++){
            int r = m0 + wm*64 + mi*16 + g;
            #pragma unroll
            for (int ni = 0; ni < 4; ni++){
                int c = n0 + wn*32 + ni*8 + 2*tg;
                float2 bb = *(const float2*)(bias + c);
                *(__half2*)(C + (size_t)r*DD + c) =
                    __floats2half2_rn(acc[mi][ni][0] + bb.x, acc[mi][ni][1] + bb.y);
                *(__half2*)(C + (size_t)(r+8)*DD + c) =
                    __floats2half2_rn(acc[mi][ni][2] + bb.x, acc[mi][ni][3] + bb.y);
            }
        }
    } else {
        int b = m0 >> 11, s0 = m0 & (SS-1);
        #pragma unroll
        for (int mi = 0; mi < 4; mi++){
            int s = s0 + wm*64 + mi*16 + g;
            #pragma unroll
            for (int ni = 0; ni < 4; ni++){
                int c = n0 + wn*32 + ni*8 + 2*tg;
                float2 bb = *(const float2*)(bias + c);
                __half* base0 = g_vpt + (size_t)(b*DD + c)*SS;
                __half* base1 = g_vpt + (size_t)(b*DD + c + 1)*SS;
                base0[s]   = __float2half_rn(acc[mi][ni][0] + bb.x);
                base1[s]   = __float2half_rn(acc[mi][ni][1] + bb.y);
                base0[s+8] = __float2half_rn(acc[mi][ni][2] + bb.x);
                base1[s+8] = __float2half_rn(acc[mi][ni][3] + bb.y);
            }
        }
    }
}

__global__ __launch_bounds__(256, 2) void scores_tc(){
    extern __shared__ unsigned sh[];
    int b = blockIdx.z;
    int m0 = blockIdx.y*128, n0 = blockIdx.x*128;
    float acc[4][4][4] = {};
    gemm_main(sh, g_qph + (size_t)(b*SS + m0)*DD, DD,
                  g_kph + (size_t)(b*SS + n0)*DD, DD, DD/BKH, acc);

    const float scale = 0.04419417382415922f;   // 1/sqrt(512)
    int lane = threadIdx.x & 31, warp = threadIdx.x >> 5;
    int wm = warp & 1, wn = warp >> 1;
    int g = lane >> 2, tg = lane & 3;
    __half* C = g_exph + (size_t)b*SS*SS;
    float rs[4][2] = {};
    #pragma unroll
    for (int mi = 0; mi < 4; mi++){
        int r = m0 + wm*64 + mi*16 + g;
        #pragma unroll
        for (int ni = 0; ni < 4; ni++){
            int c = n0 + wn*32 + ni*8 + 2*tg;
            float e0 = __expf(acc[mi][ni][0]*scale);
            float e1 = __expf(acc[mi][ni][1]*scale);
            float e2 = __expf(acc[mi][ni][2]*scale);
            float e3 = __expf(acc[mi][ni][3]*scale);
            *(__half2*)(C + (size_t)r*SS + c)     = __floats2half2_rn(e0, e1);
            *(__half2*)(C + (size_t)(r+8)*SS + c) = __floats2half2_rn(e2, e3);
            rs[mi][0] += e0 + e1;
            rs[mi][1] += e2 + e3;
        }
    }
    #pragma unroll
    for (int mi = 0; mi < 4; mi++){
        #pragma unroll
        for (int h = 0; h < 2; h++){
            float v = rs[mi][h];
            v += __shfl_xor_sync(0xffffffffu, v, 1);
            v += __shfl_xor_sync(0xffffffffu, v, 2);
            if (tg == 0)
                atomicAdd(&g_rowsum[b*SS + m0 + wm*64 + mi*16 + g + h*8], v);
        }
    }
}

__global__ __launch_bounds__(256, 2) void pv_tc(float* out){
    extern __shared__ unsigned sh[];
    int b = blockIdx.z;
    int m0 = blockIdx.y*128, n0 = blockIdx.x*128;
    float acc[4][4][4] = {};
    gemm_main(sh, g_exph + (size_t)(b*SS + m0)*SS, SS,
                  g_vpt  + (size_t)(b*DD + n0)*SS, SS, SS/BKH, acc);

    int lane = threadIdx.x & 31, warp = threadIdx.x >> 5;
    int wm = warp & 1, wn = warp >> 1;
    int g = lane >> 2, tg = lane & 3;
    #pragma unroll
    for (int mi = 0; mi < 4; mi++){
        int r = m0 + wm*64 + mi*16 + g;
        float inv0 = 1.0f / g_rowsum[b*SS + r];
        float inv1 = 1.0f / g_rowsum[b*SS + r + 8];
        #pragma unroll
        for (int ni = 0; ni < 4; ni++){
            int c = n0 + wn*32 + ni*8 + 2*tg;
            *(float2*)(out + (size_t)(b*SS + r)*DD + c) =
                make_float2(acc[mi][ni][0]*inv0, acc[mi][ni][1]*inv0);
            *(float2*)(out + (size_t)(b*SS + r + 8)*DD + c) =
                make_float2(acc[mi][ni][2]*inv1, acc[mi][ni][3]*inv1);
        }
    }
}

// ================= launch =================
extern "C" void kernel_launch(void* const* d_in, const int* in_sizes, int n_in,
                              void* d_out, int out_size)
{
    const float* q  = (const float*)d_in[0];
    const float* k  = (const float*)d_in[1];
    const float* v  = (const float*)d_in[2];
    const float* Wq = (const float*)d_in[3];
    const float* bq = (const float*)d_in[4];
    const float* Wk = (const float*)d_in[5];
    const float* bk = (const float*)d_in[6];
    const float* Wv = (const float*)d_in[7];
    const float* bv = (const float*)d_in[8];
    float* out = (float*)d_out;

    cudaFuncSetAttribute(proj_tc,   cudaFuncAttributeMaxDynamicSharedMemorySize, SMEM_BYTES);
    cudaFuncSetAttribute(scores_tc, cudaFuncAttributeMaxDynamicSharedMemorySize, SMEM_BYTES);
    cudaFuncSetAttribute(pv_tc,     cudaFuncAttributeMaxDynamicSharedMemorySize, SMEM_BYTES);

    void* p_rowsum;
    cudaGetSymbolAddress(&p_rowsum, g_rowsum);

    cvt_half<<<dim3(4096, 1, 3), 256>>>((const float4*)q, (const float4*)k, (const float4*)v);
    wt_t<<<dim3(16, 16, 3), dim3(32, 8)>>>(Wq, Wk, Wv);
    cudaMemsetAsync(p_rowsum, 0, MTOT*sizeof(float));

    proj_tc  <<<dim3(4, 128, 3), 256, SMEM_BYTES>>>(bq, bk, bv);
    scores_tc<<<dim3(16, 16, 8), 256, SMEM_BYTES>>>();
    pv_tc    <<<dim3(4, 16, 8),  256, SMEM_BYTES>>>(out);
}